// round 6
// baseline (speedup 1.0000x reference)
#include <cuda_runtime.h>
#include <cuda_bf16.h>
#include <math.h>
#include <stdint.h>

// Problem constants
#define NB   4
#define NT   512
#define NH   512
#define NV   32000
#define NS   512
#define NSDV 300
#define NTDV 512
#define MM   (NB*NT)              // 2048 rows
#define NOUT (NV+NSDV+NTDV)       // 32812
#define KK   (3*NH)               // 1536 expanded K (Ah|Ah|Al x Bh|Bl|Bh)

// Scratch (static device arrays; no allocation allowed)
__device__ float g_scores[(size_t)MM*NV];         // 262 MB
__device__ float g_p[MM*3];
__device__ float g_sumexp[MM];
__device__ int   g_src_idx[NB*NS];
__device__ int   g_tgt_idx[NB*NT];
__device__ __nv_bfloat16 g_Ap[(size_t)MM*KK];     // 6.3 MB  [m][k']
__device__ __nv_bfloat16 g_Bp[(size_t)NV*KK];     // 98 MB   [n][k'] (K-major)

// ---------------------------------------------------------------------------
__device__ __forceinline__ uint32_t smem_u32(const void* p) {
    uint32_t a;
    asm("{ .reg .u64 t; cvta.to.shared.u64 t, %1; cvt.u32.u64 %0, t; }"
        : "=r"(a) : "l"(p));
    return a;
}
__device__ __forceinline__ void cp_async16(uint32_t dst, const void* src) {
    asm volatile("cp.async.cg.shared.global [%0], [%1], 16;"
                 :: "r"(dst), "l"(src));
}
#define CP_COMMIT() asm volatile("cp.async.commit_group;")
#define CP_WAIT1()  asm volatile("cp.async.wait_group 1;")

__device__ __forceinline__ void ldmx4(uint32_t* r, uint32_t addr) {
    asm volatile("ldmatrix.sync.aligned.m8n8.x4.shared.b16 {%0,%1,%2,%3}, [%4];"
                 : "=r"(r[0]), "=r"(r[1]), "=r"(r[2]), "=r"(r[3]) : "r"(addr));
}
__device__ __forceinline__ void mma16816(float* c, const uint32_t* a,
                                         const uint32_t* b) {
    asm volatile(
        "mma.sync.aligned.m16n8k16.row.col.f32.bf16.bf16.f32 "
        "{%0,%1,%2,%3}, {%4,%5,%6,%7}, {%8,%9}, {%0,%1,%2,%3};"
        : "+f"(c[0]), "+f"(c[1]), "+f"(c[2]), "+f"(c[3])
        : "r"(a[0]), "r"(a[1]), "r"(a[2]), "r"(a[3]), "r"(b[0]), "r"(b[1]));
}

// ---------------------------------------------------------------------------
// One-hot index extraction (only needed before finalize)
// ---------------------------------------------------------------------------
__global__ void prep_idx_kernel(const float* __restrict__ smap,
                                const float* __restrict__ tmap) {
    int i = blockIdx.x * blockDim.x + threadIdx.x;   // 0..2047
    if (i >= NB*NS) return;
    {
        const float* r = smap + (size_t)i * NSDV;
        int idx = 0;
        for (int v = 0; v < NSDV; v++) if (r[v] > 0.5f) idx = v;
        g_src_idx[i] = idx;
    }
    {
        const float* r = tmap + (size_t)i * NTDV;
        int idx = 0;
        for (int v = 0; v < NTDV; v++) if (r[v] > 0.5f) idx = v;
        g_tgt_idx[i] = idx;
    }
}

// ---------------------------------------------------------------------------
// 3-way gate: p = softmax(h @ Wp + bp). One warp per row.
// ---------------------------------------------------------------------------
__global__ void p_kernel(const float* __restrict__ H,
                         const float* __restrict__ Wp,
                         const float* __restrict__ bp) {
    int warp = threadIdx.x >> 5;
    int lane = threadIdx.x & 31;
    int row  = blockIdx.x * 4 + warp;
    if (row >= MM) return;
    const float* h = H + (size_t)row * NH;
    float s0 = 0.f, s1 = 0.f, s2 = 0.f;
    for (int k = lane; k < NH; k += 32) {
        float hv = h[k];
        s0 = fmaf(hv, Wp[k*3+0], s0);
        s1 = fmaf(hv, Wp[k*3+1], s1);
        s2 = fmaf(hv, Wp[k*3+2], s2);
    }
    #pragma unroll
    for (int o = 16; o > 0; o >>= 1) {
        s0 += __shfl_down_sync(0xffffffff, s0, o);
        s1 += __shfl_down_sync(0xffffffff, s1, o);
        s2 += __shfl_down_sync(0xffffffff, s2, o);
    }
    if (lane == 0) {
        s0 += bp[0]; s1 += bp[1]; s2 += bp[2];
        float m = fmaxf(s0, fmaxf(s1, s2));
        float e0 = expf(s0 - m), e1 = expf(s1 - m), e2 = expf(s2 - m);
        float inv = 1.0f / (e0 + e1 + e2);
        g_p[row*3+0] = e0 * inv;
        g_p[row*3+1] = e1 * inv;
        g_p[row*3+2] = e2 * inv;
    }
}

// ---------------------------------------------------------------------------
// Build A' = [Ah | Ah | Al] (bf16) from fp32 hiddens; also zero g_sumexp
// (must complete before the GEMM's atomic accumulation).
// ---------------------------------------------------------------------------
__global__ void convA_kernel(const float* __restrict__ A) {
    int i = blockIdx.x * blockDim.x + threadIdx.x;   // MM*NH
    if (i < MM) g_sumexp[i] = 0.f;
    float a = A[i];
    int row = i >> 9, k = i & 511;
    __nv_bfloat16 hi = __float2bfloat16(a);
    __nv_bfloat16 lo = __float2bfloat16(a - __bfloat162float(hi));
    size_t base = (size_t)row * KK + k;
    g_Ap[base]          = hi;
    g_Ap[base + NH]     = hi;
    g_Ap[base + 2*NH]   = lo;
}

// ---------------------------------------------------------------------------
// Transpose Wv [NH][NV] -> B' [NV][K'] = [Bh | Bl | Bh]
// ---------------------------------------------------------------------------
__global__ void convB_kernel(const float* __restrict__ Wv) {
    __shared__ float t[32][33];
    int n0 = blockIdx.x * 32, k0 = blockIdx.y * 32;
    int tx = threadIdx.x, ty = threadIdx.y;   // block (32, 8)
    #pragma unroll
    for (int i = 0; i < 32; i += 8)
        t[ty+i][tx] = Wv[(size_t)(k0 + ty + i) * NV + n0 + tx];   // t[k][n]
    __syncthreads();
    #pragma unroll
    for (int i = 0; i < 32; i += 8) {
        float v = t[tx][ty+i];                 // k = k0+tx, n = n0+ty+i
        __nv_bfloat16 hi = __float2bfloat16(v);
        __nv_bfloat16 lo = __float2bfloat16(v - __bfloat162float(hi));
        size_t base = (size_t)(n0 + ty + i) * KK + k0 + tx;
        g_Bp[base]        = hi;
        g_Bp[base + NH]   = lo;
        g_Bp[base + 2*NH] = hi;
    }
}

// ---------------------------------------------------------------------------
// mma.sync GEMM: g_scores = A' @ B'^T + bias, fused per-row partial sumexp.
// 128x128 tiles, BK=64, 3-stage cp.async pipeline, 8 warps of 32x64.
// __launch_bounds__(256, 2): target 2 CTAs/SM (<=124 regs).
// ---------------------------------------------------------------------------
#define BM 128
#define BN 128
#define BK 64
#define NKITER (KK/BK)        // 24
#define STAGE_B 32768         // A tile 16KB + B tile 16KB
#define SMEM_GEMM (3*STAGE_B) // 96 KB

__global__ __launch_bounds__(256, 2)
void gemm_mma_kernel(const float* __restrict__ bias) {
    extern __shared__ char smem[];
    const uint32_t sb = smem_u32(smem);
    const int tid  = threadIdx.x;
    const int w    = tid >> 5;
    const int lane = tid & 31;
    const int bm   = blockIdx.y * BM;    // 16
    const int bn   = blockIdx.x * BN;    // 250
    const int wm   = w & 3;              // warp row (4)
    const int wn   = w >> 2;             // warp col (2)

    float acc[2][8][4];
    #pragma unroll
    for (int i = 0; i < 2; i++)
        #pragma unroll
        for (int j = 0; j < 8; j++)
            #pragma unroll
            for (int q = 0; q < 4; q++) acc[i][j][q] = 0.f;

#define LOAD_STAGE(kt, s) do {                                                  \
    uint32_t base = sb + (uint32_t)(s) * STAGE_B;                               \
    int k0 = (kt) * BK;                                                         \
    _Pragma("unroll")                                                           \
    for (int i = 0; i < 4; i++) {                                               \
        int g   = tid + i * 256;                                                \
        int row = g >> 3, c = g & 7;                                            \
        uint32_t sw = (uint32_t)row * 128 + (uint32_t)((c ^ (row & 7)) * 16);   \
        cp_async16(base + sw,                                                   \
                   g_Ap + (size_t)(bm + row) * KK + k0 + c * 8);                \
        cp_async16(base + 16384 + sw,                                           \
                   g_Bp + (size_t)(bn + row) * KK + k0 + c * 8);                \
    }                                                                           \
    CP_COMMIT();                                                                \
} while (0)

    LOAD_STAGE(0, 0);
    LOAD_STAGE(1, 1);

    for (int kt = 0; kt < NKITER; kt++) {
        const int s = kt % 3;
        CP_WAIT1();
        __syncthreads();
        if (kt + 2 < NKITER) LOAD_STAGE(kt + 2, (kt + 2) % 3);

        const uint32_t abase = sb + (uint32_t)s * STAGE_B;
        const uint32_t bbase = abase + 16384;
        #pragma unroll
        for (int ks = 0; ks < 4; ks++) {
            uint32_t a[2][4];
            #pragma unroll
            for (int i = 0; i < 2; i++) {
                int row = wm * 32 + i * 16 + (lane & 15);
                int ch  = ks * 2 + (lane >> 4);
                uint32_t addr = abase + (uint32_t)row * 128
                              + (uint32_t)((ch ^ (row & 7)) * 16);
                ldmx4(a[i], addr);
            }
            uint32_t b[8][2];
            #pragma unroll
            for (int jj = 0; jj < 4; jj++) {
                int row = wn * 64 + jj * 16 + (lane & 15);
                int ch  = ks * 2 + (lane >> 4);
                uint32_t addr = bbase + (uint32_t)row * 128
                              + (uint32_t)((ch ^ (row & 7)) * 16);
                uint32_t r[4];
                ldmx4(r, addr);
                b[2*jj][0]   = r[0]; b[2*jj][1]   = r[2];
                b[2*jj+1][0] = r[1]; b[2*jj+1][1] = r[3];
            }
            #pragma unroll
            for (int i = 0; i < 2; i++)
                #pragma unroll
                for (int j = 0; j < 8; j++)
                    mma16816(acc[i][j], a[i], b[j]);
        }
    }

    // epilogue: bias add, store scores, per-row partial sum of exp
    #pragma unroll
    for (int i = 0; i < 2; i++) {
        const int row = bm + wm * 32 + i * 16 + (lane >> 2);
        float s0 = 0.f, s1 = 0.f;       // rows row, row+8
        #pragma unroll
        for (int j = 0; j < 8; j++) {
            const int col = bn + wn * 64 + j * 8 + (lane & 3) * 2;
            const float b0 = bias[col], b1 = bias[col + 1];
            float v00 = acc[i][j][0] + b0, v01 = acc[i][j][1] + b1;
            float v10 = acc[i][j][2] + b0, v11 = acc[i][j][3] + b1;
            *(float2*)(g_scores + (size_t)row * NV + col)       = make_float2(v00, v01);
            *(float2*)(g_scores + (size_t)(row + 8) * NV + col) = make_float2(v10, v11);
            // masked vocab index 0 contributes nothing to the softmax sum
            s0 += ((col == 0) ? 0.f : __expf(v00)) + __expf(v01);
            s1 += ((col == 0) ? 0.f : __expf(v10)) + __expf(v11);
        }
        s0 += __shfl_xor_sync(0xffffffff, s0, 1);
        s0 += __shfl_xor_sync(0xffffffff, s0, 2);
        s1 += __shfl_xor_sync(0xffffffff, s1, 1);
        s1 += __shfl_xor_sync(0xffffffff, s1, 2);
        if ((lane & 3) == 0) {
            atomicAdd(&g_sumexp[row],     s0);
            atomicAdd(&g_sumexp[row + 8], s1);
        }
    }
}

// ---------------------------------------------------------------------------
// Per-row: single pass over scores (p = exp(s)*pg/sum), one-hot copy scatters,
// concat write, fused argmax.
// ---------------------------------------------------------------------------
__global__ __launch_bounds__(256)
void finalize_kernel(const float* __restrict__ satt,
                     const float* __restrict__ tatt,
                     float* __restrict__ out) {
    const int row = blockIdx.x;
    const int b   = row / NT;
    const int tid = threadIdx.x;

    __shared__ float red[256];
    __shared__ int   redi[256];
    __shared__ float src_acc[NSDV];
    __shared__ float tgt_acc[NTDV];

    for (int i = tid; i < NSDV; i += 256) src_acc[i] = 0.f;
    for (int i = tid; i < NTDV; i += 256) tgt_acc[i] = 0.f;
    __syncthreads();

    for (int s = tid; s < NS; s += 256)
        atomicAdd(&src_acc[g_src_idx[b*NS + s]], satt[(size_t)row*NS + s]);
    for (int n = tid; n < NT; n += 256)
        atomicAdd(&tgt_acc[g_tgt_idx[b*NT + n]], tatt[(size_t)row*NTDV + n]);

    const float pg    = g_p[row*3+2];
    const float pcs   = g_p[row*3+0];
    const float pct   = g_p[row*3+1];
    const float scale = pg / g_sumexp[row];

    const float4* srow4 = (const float4*)(g_scores + (size_t)row * NV);
    float* orow = out + (size_t)row * NOUT;
    float4* orow4 = (float4*)orow;
    float   bmax = -INFINITY;
    int     bidx = 0;

    for (int i = tid; i < NV/4; i += 256) {
        float4 v = srow4[i];
        float4 p;
        p.x = __expf(v.x) * scale;
        p.y = __expf(v.y) * scale;
        p.z = __expf(v.z) * scale;
        p.w = __expf(v.w) * scale;
        if (i == 0) p.x = 0.f;
        orow4[i] = p;
        int base = i * 4;
        if (p.x > bmax) { bmax = p.x; bidx = base;   }
        if (p.y > bmax) { bmax = p.y; bidx = base+1; }
        if (p.z > bmax) { bmax = p.z; bidx = base+2; }
        if (p.w > bmax) { bmax = p.w; bidx = base+3; }
    }
    for (int v = tid; v < NSDV; v += 256) {
        float pv = pcs * src_acc[v];
        orow[NV + v] = pv;
        int gi = NV + v;
        if (pv > bmax || (pv == bmax && gi < bidx)) { bmax = pv; bidx = gi; }
    }
    for (int v = tid; v < NTDV; v += 256) {
        float pv = pct * tgt_acc[v];
        orow[NV + NSDV + v] = pv;
        int gi = NV + NSDV + v;
        if (pv > bmax || (pv == bmax && gi < bidx)) { bmax = pv; bidx = gi; }
    }

    red[tid]  = bmax;
    redi[tid] = bidx;
    __syncthreads();
    for (int o = 128; o > 0; o >>= 1) {
        if (tid < o) {
            float v2 = red[tid + o]; int i2 = redi[tid + o];
            if (v2 > red[tid] || (v2 == red[tid] && i2 < redi[tid])) {
                red[tid] = v2; redi[tid] = i2;
            }
        }
        __syncthreads();
    }
    if (tid == 0)
        out[(size_t)MM * NOUT + row] = (float)redi[0];
}

// ---------------------------------------------------------------------------
extern "C" void kernel_launch(void* const* d_in, const int* in_sizes, int n_in,
                              void* d_out, int out_size) {
    const float* hiddens = (const float*)d_in[0];
    const float* Wp      = (const float*)d_in[1];
    const float* bp      = (const float*)d_in[2];
    const float* Wv      = (const float*)d_in[3];
    const float* bv      = (const float*)d_in[4];
    const float* satt    = (const float*)d_in[5];
    const float* smap    = (const float*)d_in[6];
    const float* tatt    = (const float*)d_in[7];
    const float* tmap    = (const float*)d_in[8];
    float* out = (float*)d_out;

    cudaFuncSetAttribute(gemm_mma_kernel,
                         cudaFuncAttributeMaxDynamicSharedMemorySize, SMEM_GEMM);

    // gemm in launch slot 4 -> gets ncu-captured
    convA_kernel<<<(MM*NH)/256, 256>>>(hiddens);               // 1 (also zeroes sumexp)
    convB_kernel<<<dim3(NV/32, NH/32), dim3(32, 8)>>>(Wv);     // 2
    p_kernel<<<MM/4, 128>>>(hiddens, Wp, bp);                  // 3
    gemm_mma_kernel<<<dim3(NV/BN, MM/BM), 256, SMEM_GEMM>>>(bv); // 4
    prep_idx_kernel<<<8, 256>>>(smap, tmap);                   // 5
    finalize_kernel<<<MM, 256>>>(satt, tatt, out);             // 6
}

// round 7
// speedup vs baseline: 1.0134x; 1.0134x over previous
#include <cuda_runtime.h>
#include <cuda_bf16.h>
#include <math.h>
#include <stdint.h>

// Problem constants
#define NB   4
#define NT   512
#define NH   512
#define NV   32000
#define NS   512
#define NSDV 300
#define NTDV 512
#define MM   (NB*NT)              // 2048 rows
#define NOUT (NV+NSDV+NTDV)       // 32812
#define KK   (3*NH)               // 1536 expanded K (Ah|Ah|Al x Bh|Bl|Bh)

// Scratch (static device arrays; no allocation allowed)
__device__ float g_scores[(size_t)MM*NV];         // 262 MB
__device__ float g_p[MM*3];
__device__ float g_sumexp[MM];
__device__ int   g_src_idx[NB*NS];
__device__ int   g_tgt_idx[NB*NT];
__device__ __nv_bfloat16 g_Ap[(size_t)MM*KK];     // 6.3 MB  [m][k']
__device__ __nv_bfloat16 g_Bp[(size_t)NV*KK];     // 98 MB   [n][k'] (K-major)

// ---------------------------------------------------------------------------
__device__ __forceinline__ uint32_t smem_u32(const void* p) {
    uint32_t a;
    asm("{ .reg .u64 t; cvta.to.shared.u64 t, %1; cvt.u32.u64 %0, t; }"
        : "=r"(a) : "l"(p));
    return a;
}
__device__ __forceinline__ void cp_async16(uint32_t dst, const void* src) {
    asm volatile("cp.async.cg.shared.global [%0], [%1], 16;"
                 :: "r"(dst), "l"(src));
}
#define CP_COMMIT() asm volatile("cp.async.commit_group;")
#define CP_WAIT1()  asm volatile("cp.async.wait_group 1;")

__device__ __forceinline__ void ldmx4(uint32_t* r, uint32_t addr) {
    asm volatile("ldmatrix.sync.aligned.m8n8.x4.shared.b16 {%0,%1,%2,%3}, [%4];"
                 : "=r"(r[0]), "=r"(r[1]), "=r"(r[2]), "=r"(r[3]) : "r"(addr));
}
__device__ __forceinline__ void mma16816(float* c, const uint32_t* a,
                                         const uint32_t* b) {
    asm volatile(
        "mma.sync.aligned.m16n8k16.row.col.f32.bf16.bf16.f32 "
        "{%0,%1,%2,%3}, {%4,%5,%6,%7}, {%8,%9}, {%0,%1,%2,%3};"
        : "+f"(c[0]), "+f"(c[1]), "+f"(c[2]), "+f"(c[3])
        : "r"(a[0]), "r"(a[1]), "r"(a[2]), "r"(a[3]), "r"(b[0]), "r"(b[1]));
}

// ---------------------------------------------------------------------------
// One-hot index extraction
// ---------------------------------------------------------------------------
__global__ void prep_idx_kernel(const float* __restrict__ smap,
                                const float* __restrict__ tmap) {
    int i = blockIdx.x * blockDim.x + threadIdx.x;   // 0..2047
    if (i >= NB*NS) return;
    {
        const float* r = smap + (size_t)i * NSDV;
        int idx = 0;
        for (int v = 0; v < NSDV; v++) if (r[v] > 0.5f) idx = v;
        g_src_idx[i] = idx;
    }
    {
        const float* r = tmap + (size_t)i * NTDV;
        int idx = 0;
        for (int v = 0; v < NTDV; v++) if (r[v] > 0.5f) idx = v;
        g_tgt_idx[i] = idx;
    }
}

// ---------------------------------------------------------------------------
// 3-way gate: p = softmax(h @ Wp + bp). One warp per row.
// ---------------------------------------------------------------------------
__global__ void p_kernel(const float* __restrict__ H,
                         const float* __restrict__ Wp,
                         const float* __restrict__ bp) {
    int warp = threadIdx.x >> 5;
    int lane = threadIdx.x & 31;
    int row  = blockIdx.x * 4 + warp;
    if (row >= MM) return;
    const float* h = H + (size_t)row * NH;
    float s0 = 0.f, s1 = 0.f, s2 = 0.f;
    for (int k = lane; k < NH; k += 32) {
        float hv = h[k];
        s0 = fmaf(hv, Wp[k*3+0], s0);
        s1 = fmaf(hv, Wp[k*3+1], s1);
        s2 = fmaf(hv, Wp[k*3+2], s2);
    }
    #pragma unroll
    for (int o = 16; o > 0; o >>= 1) {
        s0 += __shfl_down_sync(0xffffffff, s0, o);
        s1 += __shfl_down_sync(0xffffffff, s1, o);
        s2 += __shfl_down_sync(0xffffffff, s2, o);
    }
    if (lane == 0) {
        s0 += bp[0]; s1 += bp[1]; s2 += bp[2];
        float m = fmaxf(s0, fmaxf(s1, s2));
        float e0 = expf(s0 - m), e1 = expf(s1 - m), e2 = expf(s2 - m);
        float inv = 1.0f / (e0 + e1 + e2);
        g_p[row*3+0] = e0 * inv;
        g_p[row*3+1] = e1 * inv;
        g_p[row*3+2] = e2 * inv;
    }
}

// ---------------------------------------------------------------------------
// Build A' = [Ah | Ah | Al] (bf16) from fp32 hiddens; also zero g_sumexp
// ---------------------------------------------------------------------------
__global__ void convA_kernel(const float* __restrict__ A) {
    int i = blockIdx.x * blockDim.x + threadIdx.x;   // MM*NH
    if (i < MM) g_sumexp[i] = 0.f;
    float a = A[i];
    int row = i >> 9, k = i & 511;
    __nv_bfloat16 hi = __float2bfloat16(a);
    __nv_bfloat16 lo = __float2bfloat16(a - __bfloat162float(hi));
    size_t base = (size_t)row * KK + k;
    g_Ap[base]          = hi;
    g_Ap[base + NH]     = hi;
    g_Ap[base + 2*NH]   = lo;
}

// ---------------------------------------------------------------------------
// Transpose Wv [NH][NV] -> B' [NV][K'] = [Bh | Bl | Bh]
// ---------------------------------------------------------------------------
__global__ void convB_kernel(const float* __restrict__ Wv) {
    __shared__ float t[32][33];
    int n0 = blockIdx.x * 32, k0 = blockIdx.y * 32;
    int tx = threadIdx.x, ty = threadIdx.y;   // block (32, 8)
    #pragma unroll
    for (int i = 0; i < 32; i += 8)
        t[ty+i][tx] = Wv[(size_t)(k0 + ty + i) * NV + n0 + tx];   // t[k][n]
    __syncthreads();
    #pragma unroll
    for (int i = 0; i < 32; i += 8) {
        float v = t[tx][ty+i];                 // k = k0+tx, n = n0+ty+i
        __nv_bfloat16 hi = __float2bfloat16(v);
        __nv_bfloat16 lo = __float2bfloat16(v - __bfloat162float(hi));
        size_t base = (size_t)(n0 + ty + i) * KK + k0 + tx;
        g_Bp[base]        = hi;
        g_Bp[base + NH]   = lo;
        g_Bp[base + 2*NH] = hi;
    }
}

// ---------------------------------------------------------------------------
// mma.sync GEMM with strength-reduced addressing.
// 128x128 tiles, BK=64, 3-stage cp.async pipeline, 8 warps of 32x64.
// ---------------------------------------------------------------------------
#define BM 128
#define BN 128
#define BK 64
#define NKITER (KK/BK)        // 24
#define STAGE_B 32768         // A tile 16KB + B tile 16KB
#define SMEM_GEMM (3*STAGE_B) // 96 KB

__global__ __launch_bounds__(256, 2)
void gemm_mma_kernel(const float* __restrict__ bias) {
    extern __shared__ char smem[];
    const uint32_t sb = smem_u32(smem);
    const int tid  = threadIdx.x;
    const int w    = tid >> 5;
    const int lane = tid & 31;
    const int bm   = blockIdx.y * BM;    // 16
    const int bn   = blockIdx.x * BN;    // 250
    const int wm   = w & 3;              // warp row (4)
    const int wn   = w >> 2;             // warp col (2)

    float acc[2][8][4];
    #pragma unroll
    for (int i = 0; i < 2; i++)
        #pragma unroll
        for (int j = 0; j < 8; j++)
            #pragma unroll
            for (int q = 0; q < 4; q++) acc[i][j][q] = 0.f;

    // --- strength-reduced loader state (per thread) ---
    const int lr = tid >> 3;             // load row 0..31
    const int lc = tid & 7;              // 16B chunk 0..7
    const __nv_bfloat16* aptr = g_Ap + (size_t)(bm + lr) * KK + lc * 8;
    const __nv_bfloat16* bptr = g_Bp + (size_t)(bn + lr) * KK + lc * 8;
    const uint32_t sw0 = (uint32_t)lr * 128 + (uint32_t)((lc ^ (lr & 7)) * 16);

#define LOAD_STAGE(s) do {                                                      \
    uint32_t d = sb + (uint32_t)(s) * STAGE_B + sw0;                            \
    _Pragma("unroll")                                                           \
    for (int i = 0; i < 4; i++) {                                               \
        cp_async16(d + i * 4096,         aptr + (size_t)i * 32 * KK);           \
        cp_async16(d + 16384 + i * 4096, bptr + (size_t)i * 32 * KK);           \
    }                                                                           \
    CP_COMMIT();                                                                \
    aptr += BK; bptr += BK;                                                     \
} while (0)

    // --- strength-reduced ldmatrix bases (per thread) ---
    const uint32_t lnx = (uint32_t)(lane >> 4) * 16;   // ln16*16 (bit 4)
    uint32_t rp_a[2], rp_b[4];
    #pragma unroll
    for (int i = 0; i < 2; i++) {
        int row = wm * 32 + i * 16 + (lane & 15);
        rp_a[i] = (uint32_t)row * 128 + (lnx ^ (uint32_t)((row & 7) * 16));
    }
    #pragma unroll
    for (int jj = 0; jj < 4; jj++) {
        int row = wn * 64 + jj * 16 + (lane & 15);
        rp_b[jj] = (uint32_t)row * 128 + (lnx ^ (uint32_t)((row & 7) * 16));
    }

    LOAD_STAGE(0);
    LOAD_STAGE(1);

    for (int kt = 0; kt < NKITER; kt++) {
        const int s = kt % 3;
        CP_WAIT1();
        __syncthreads();
        if (kt + 2 < NKITER) LOAD_STAGE((kt + 2) % 3);

        const uint32_t abase = sb + (uint32_t)s * STAGE_B;
        const uint32_t bbase = abase + 16384;
        #pragma unroll
        for (int ks = 0; ks < 4; ks++) {
            const uint32_t kx = (uint32_t)ks << 5;
            uint32_t a[2][4];
            #pragma unroll
            for (int i = 0; i < 2; i++)
                ldmx4(a[i], abase + (rp_a[i] ^ kx));
            uint32_t b[8][2];
            #pragma unroll
            for (int jj = 0; jj < 4; jj++) {
                uint32_t r[4];
                ldmx4(r, bbase + (rp_b[jj] ^ kx));
                b[2*jj][0]   = r[0]; b[2*jj][1]   = r[2];
                b[2*jj+1][0] = r[1]; b[2*jj+1][1] = r[3];
            }
            #pragma unroll
            for (int i = 0; i < 2; i++)
                #pragma unroll
                for (int j = 0; j < 8; j++)
                    mma16816(acc[i][j], a[i], b[j]);
        }
    }

    // epilogue: bias add, store scores, per-row partial sum of exp
    #pragma unroll
    for (int i = 0; i < 2; i++) {
        const int row = bm + wm * 32 + i * 16 + (lane >> 2);
        float s0 = 0.f, s1 = 0.f;       // rows row, row+8
        #pragma unroll
        for (int j = 0; j < 8; j++) {
            const int col = bn + wn * 64 + j * 8 + (lane & 3) * 2;
            const float b0 = bias[col], b1 = bias[col + 1];
            float v00 = acc[i][j][0] + b0, v01 = acc[i][j][1] + b1;
            float v10 = acc[i][j][2] + b0, v11 = acc[i][j][3] + b1;
            *(float2*)(g_scores + (size_t)row * NV + col)       = make_float2(v00, v01);
            *(float2*)(g_scores + (size_t)(row + 8) * NV + col) = make_float2(v10, v11);
            s0 += ((col == 0) ? 0.f : __expf(v00)) + __expf(v01);
            s1 += ((col == 0) ? 0.f : __expf(v10)) + __expf(v11);
        }
        s0 += __shfl_xor_sync(0xffffffff, s0, 1);
        s0 += __shfl_xor_sync(0xffffffff, s0, 2);
        s1 += __shfl_xor_sync(0xffffffff, s1, 1);
        s1 += __shfl_xor_sync(0xffffffff, s1, 2);
        if ((lane & 3) == 0) {
            atomicAdd(&g_sumexp[row],     s0);
            atomicAdd(&g_sumexp[row + 8], s1);
        }
    }
}

// ---------------------------------------------------------------------------
// Per-row: single pass over scores (p = exp(s)*pg/sum), one-hot copy scatters,
// concat write, fused argmax.
// ---------------------------------------------------------------------------
__global__ __launch_bounds__(256)
void finalize_kernel(const float* __restrict__ satt,
                     const float* __restrict__ tatt,
                     float* __restrict__ out) {
    const int row = blockIdx.x;
    const int b   = row / NT;
    const int tid = threadIdx.x;

    __shared__ float red[256];
    __shared__ int   redi[256];
    __shared__ float src_acc[NSDV];
    __shared__ float tgt_acc[NTDV];

    for (int i = tid; i < NSDV; i += 256) src_acc[i] = 0.f;
    for (int i = tid; i < NTDV; i += 256) tgt_acc[i] = 0.f;
    __syncthreads();

    for (int s = tid; s < NS; s += 256)
        atomicAdd(&src_acc[g_src_idx[b*NS + s]], satt[(size_t)row*NS + s]);
    for (int n = tid; n < NT; n += 256)
        atomicAdd(&tgt_acc[g_tgt_idx[b*NT + n]], tatt[(size_t)row*NTDV + n]);

    const float pg    = g_p[row*3+2];
    const float pcs   = g_p[row*3+0];
    const float pct   = g_p[row*3+1];
    const float scale = pg / g_sumexp[row];

    const float4* srow4 = (const float4*)(g_scores + (size_t)row * NV);
    float* orow = out + (size_t)row * NOUT;
    float4* orow4 = (float4*)orow;
    float   bmax = -INFINITY;
    int     bidx = 0;

    for (int i = tid; i < NV/4; i += 256) {
        float4 v = srow4[i];
        float4 p;
        p.x = __expf(v.x) * scale;
        p.y = __expf(v.y) * scale;
        p.z = __expf(v.z) * scale;
        p.w = __expf(v.w) * scale;
        if (i == 0) p.x = 0.f;
        orow4[i] = p;
        int base = i * 4;
        if (p.x > bmax) { bmax = p.x; bidx = base;   }
        if (p.y > bmax) { bmax = p.y; bidx = base+1; }
        if (p.z > bmax) { bmax = p.z; bidx = base+2; }
        if (p.w > bmax) { bmax = p.w; bidx = base+3; }
    }
    for (int v = tid; v < NSDV; v += 256) {
        float pv = pcs * src_acc[v];
        orow[NV + v] = pv;
        int gi = NV + v;
        if (pv > bmax || (pv == bmax && gi < bidx)) { bmax = pv; bidx = gi; }
    }
    for (int v = tid; v < NTDV; v += 256) {
        float pv = pct * tgt_acc[v];
        orow[NV + NSDV + v] = pv;
        int gi = NV + NSDV + v;
        if (pv > bmax || (pv == bmax && gi < bidx)) { bmax = pv; bidx = gi; }
    }

    red[tid]  = bmax;
    redi[tid] = bidx;
    __syncthreads();
    for (int o = 128; o > 0; o >>= 1) {
        if (tid < o) {
            float v2 = red[tid + o]; int i2 = redi[tid + o];
            if (v2 > red[tid] || (v2 == red[tid] && i2 < redi[tid])) {
                red[tid] = v2; redi[tid] = i2;
            }
        }
        __syncthreads();
    }
    if (tid == 0)
        out[(size_t)MM * NOUT + row] = (float)redi[0];
}

// ---------------------------------------------------------------------------
extern "C" void kernel_launch(void* const* d_in, const int* in_sizes, int n_in,
                              void* d_out, int out_size) {
    const float* hiddens = (const float*)d_in[0];
    const float* Wp      = (const float*)d_in[1];
    const float* bp      = (const float*)d_in[2];
    const float* Wv      = (const float*)d_in[3];
    const float* bv      = (const float*)d_in[4];
    const float* satt    = (const float*)d_in[5];
    const float* smap    = (const float*)d_in[6];
    const float* tatt    = (const float*)d_in[7];
    const float* tmap    = (const float*)d_in[8];
    float* out = (float*)d_out;

    cudaFuncSetAttribute(gemm_mma_kernel,
                         cudaFuncAttributeMaxDynamicSharedMemorySize, SMEM_GEMM);

    // gemm in launch slot 4 -> gets ncu-captured
    convA_kernel<<<(MM*NH)/256, 256>>>(hiddens);               // 1 (also zeroes sumexp)
    convB_kernel<<<dim3(NV/32, NH/32), dim3(32, 8)>>>(Wv);     // 2
    p_kernel<<<MM/4, 128>>>(hiddens, Wp, bp);                  // 3
    gemm_mma_kernel<<<dim3(NV/BN, MM/BM), 256, SMEM_GEMM>>>(bv); // 4
    prep_idx_kernel<<<8, 256>>>(smap, tmap);                   // 5
    finalize_kernel<<<MM, 256>>>(satt, tatt, out);             // 6
}

// round 8
// speedup vs baseline: 1.0390x; 1.0253x over previous
#include <cuda_runtime.h>
#include <cuda_bf16.h>
#include <math.h>
#include <stdint.h>

// Problem constants
#define NB   4
#define NT   512
#define NH   512
#define NV   32000
#define NS   512
#define NSDV 300
#define NTDV 512
#define MM   (NB*NT)              // 2048 rows
#define NOUT (NV+NSDV+NTDV)       // 32812
#define KK   (3*NH)               // 1536 expanded K (Ah|Ah|Al x Bh|Bl|Bh)

// Scratch (static device arrays; no allocation allowed)
__device__ float g_scores[(size_t)MM*NV];         // 262 MB
__device__ float g_p[MM*3];
__device__ float g_sumexp[MM];
__device__ unsigned long long g_amax[MM];
__device__ int   g_src_idx[NB*NS];
__device__ int   g_tgt_idx[NB*NT];
__device__ __nv_bfloat16 g_Ap[(size_t)MM*KK];     // 6.3 MB  [m][k']
__device__ __nv_bfloat16 g_Bp[(size_t)NV*KK];     // 98 MB   [n][k'] (K-major)

// ---------------------------------------------------------------------------
__device__ __forceinline__ uint32_t smem_u32(const void* p) {
    uint32_t a;
    asm("{ .reg .u64 t; cvta.to.shared.u64 t, %1; cvt.u32.u64 %0, t; }"
        : "=r"(a) : "l"(p));
    return a;
}
__device__ __forceinline__ void cp_async16(uint32_t dst, const void* src) {
    asm volatile("cp.async.cg.shared.global [%0], [%1], 16;"
                 :: "r"(dst), "l"(src));
}
#define CP_COMMIT() asm volatile("cp.async.commit_group;")
#define CP_WAIT1()  asm volatile("cp.async.wait_group 1;")

__device__ __forceinline__ void ldmx4(uint32_t* r, uint32_t addr) {
    asm volatile("ldmatrix.sync.aligned.m8n8.x4.shared.b16 {%0,%1,%2,%3}, [%4];"
                 : "=r"(r[0]), "=r"(r[1]), "=r"(r[2]), "=r"(r[3]) : "r"(addr));
}
__device__ __forceinline__ void mma16816(float* c, const uint32_t* a,
                                         const uint32_t* b) {
    asm volatile(
        "mma.sync.aligned.m16n8k16.row.col.f32.bf16.bf16.f32 "
        "{%0,%1,%2,%3}, {%4,%5,%6,%7}, {%8,%9}, {%0,%1,%2,%3};"
        : "+f"(c[0]), "+f"(c[1]), "+f"(c[2]), "+f"(c[3])
        : "r"(a[0]), "r"(a[1]), "r"(a[2]), "r"(a[3]), "r"(b[0]), "r"(b[1]));
}

// ---------------------------------------------------------------------------
// One-hot index extraction
// ---------------------------------------------------------------------------
__global__ void prep_idx_kernel(const float* __restrict__ smap,
                                const float* __restrict__ tmap) {
    int i = blockIdx.x * blockDim.x + threadIdx.x;   // 0..2047
    if (i >= NB*NS) return;
    {
        const float* r = smap + (size_t)i * NSDV;
        int idx = 0;
        for (int v = 0; v < NSDV; v++) if (r[v] > 0.5f) idx = v;
        g_src_idx[i] = idx;
    }
    {
        const float* r = tmap + (size_t)i * NTDV;
        int idx = 0;
        for (int v = 0; v < NTDV; v++) if (r[v] > 0.5f) idx = v;
        g_tgt_idx[i] = idx;
    }
}

// ---------------------------------------------------------------------------
// Merged: 3-way gate p = softmax(h@Wp+bp), A' = [Ah|Ah|Al] build,
// zero g_sumexp / g_amax. One warp per row.
// ---------------------------------------------------------------------------
__global__ void p_conv_kernel(const float* __restrict__ H,
                              const float* __restrict__ Wp,
                              const float* __restrict__ bp) {
    int warp = threadIdx.x >> 5;
    int lane = threadIdx.x & 31;
    int row  = blockIdx.x * 4 + warp;
    if (row >= MM) return;
    const float* h = H + (size_t)row * NH;
    __nv_bfloat16* ap = g_Ap + (size_t)row * KK;
    float s0 = 0.f, s1 = 0.f, s2 = 0.f;
    #pragma unroll
    for (int k = lane; k < NH; k += 32) {
        float hv = h[k];
        __nv_bfloat16 hi = __float2bfloat16(hv);
        __nv_bfloat16 lo = __float2bfloat16(hv - __bfloat162float(hi));
        ap[k]        = hi;
        ap[k + NH]   = hi;
        ap[k + 2*NH] = lo;
        s0 = fmaf(hv, Wp[k*3+0], s0);
        s1 = fmaf(hv, Wp[k*3+1], s1);
        s2 = fmaf(hv, Wp[k*3+2], s2);
    }
    #pragma unroll
    for (int o = 16; o > 0; o >>= 1) {
        s0 += __shfl_down_sync(0xffffffff, s0, o);
        s1 += __shfl_down_sync(0xffffffff, s1, o);
        s2 += __shfl_down_sync(0xffffffff, s2, o);
    }
    if (lane == 0) {
        g_sumexp[row] = 0.f;
        g_amax[row]   = 0ull;
        s0 += bp[0]; s1 += bp[1]; s2 += bp[2];
        float m = fmaxf(s0, fmaxf(s1, s2));
        float e0 = expf(s0 - m), e1 = expf(s1 - m), e2 = expf(s2 - m);
        float inv = 1.0f / (e0 + e1 + e2);
        g_p[row*3+0] = e0 * inv;
        g_p[row*3+1] = e1 * inv;
        g_p[row*3+2] = e2 * inv;
    }
}

// ---------------------------------------------------------------------------
// Transpose Wv [NH][NV] -> B' [NV][K'] = [Bh | Bl | Bh]
// ---------------------------------------------------------------------------
__global__ void convB_kernel(const float* __restrict__ Wv) {
    __shared__ float t[32][33];
    int n0 = blockIdx.x * 32, k0 = blockIdx.y * 32;
    int tx = threadIdx.x, ty = threadIdx.y;   // block (32, 8)
    #pragma unroll
    for (int i = 0; i < 32; i += 8)
        t[ty+i][tx] = Wv[(size_t)(k0 + ty + i) * NV + n0 + tx];   // t[k][n]
    __syncthreads();
    #pragma unroll
    for (int i = 0; i < 32; i += 8) {
        float v = t[tx][ty+i];                 // k = k0+tx, n = n0+ty+i
        __nv_bfloat16 hi = __float2bfloat16(v);
        __nv_bfloat16 lo = __float2bfloat16(v - __bfloat162float(hi));
        size_t base = (size_t)(n0 + ty + i) * KK + k0 + tx;
        g_Bp[base]        = hi;
        g_Bp[base + NH]   = lo;
        g_Bp[base + 2*NH] = hi;
    }
}

// ---------------------------------------------------------------------------
// mma.sync GEMM, higher occupancy config: 128x64 CTA tiles, 8 warps of
// 32x32, 3 CTAs/SM target (acc=32 regs). 3-stage cp.async pipeline.
// ---------------------------------------------------------------------------
#define BM 128
#define BN 64
#define BK 64
#define NKITER (KK/BK)        // 24
#define A_STG   16384         // 128 rows x 128 B
#define B_STG   8192          // 64 rows x 128 B
#define STAGE_B (A_STG+B_STG) // 24 KB
#define SMEM_GEMM (3*STAGE_B) // 72 KB

__global__ __launch_bounds__(256, 3)
void gemm_mma_kernel(const float* __restrict__ bias) {
    extern __shared__ char smem[];
    const uint32_t sb = smem_u32(smem);
    const int tid  = threadIdx.x;
    const int w    = tid >> 5;
    const int lane = tid & 31;
    const int bm   = blockIdx.y * BM;    // 16
    const int bn   = blockIdx.x * BN;    // 500
    const int wm   = w & 3;              // warp row (4): 32 M each
    const int wn   = w >> 2;             // warp col (2): 32 N each

    float acc[2][4][4];
    #pragma unroll
    for (int i = 0; i < 2; i++)
        #pragma unroll
        for (int j = 0; j < 4; j++)
            #pragma unroll
            for (int q = 0; q < 4; q++) acc[i][j][q] = 0.f;

    // --- strength-reduced loader state ---
    const int lr = tid >> 3;             // 0..31
    const int lc = tid & 7;              // 16B chunk
    const __nv_bfloat16* aptr = g_Ap + (size_t)(bm + lr) * KK + lc * 8;
    const __nv_bfloat16* bptr = g_Bp + (size_t)(bn + lr) * KK + lc * 8;
    const uint32_t sw0 = (uint32_t)lr * 128 + (uint32_t)((lc ^ (lr & 7)) * 16);

#define LOAD_STAGE(s) do {                                                      \
    uint32_t d = sb + (uint32_t)(s) * STAGE_B + sw0;                            \
    _Pragma("unroll")                                                           \
    for (int i = 0; i < 4; i++)                                                 \
        cp_async16(d + i * 4096, aptr + (size_t)i * 32 * KK);                   \
    _Pragma("unroll")                                                           \
    for (int i = 0; i < 2; i++)                                                 \
        cp_async16(d + A_STG + i * 4096, bptr + (size_t)i * 32 * KK);           \
    CP_COMMIT();                                                                \
    aptr += BK; bptr += BK;                                                     \
} while (0)

    // --- strength-reduced ldmatrix bases ---
    const uint32_t lnx = (uint32_t)(lane >> 4) * 16;
    uint32_t rp_a[2], rp_b[2];
    #pragma unroll
    for (int i = 0; i < 2; i++) {
        int row = wm * 32 + i * 16 + (lane & 15);
        rp_a[i] = (uint32_t)row * 128 + (lnx ^ (uint32_t)((row & 7) * 16));
    }
    #pragma unroll
    for (int jj = 0; jj < 2; jj++) {
        int row = wn * 32 + jj * 16 + (lane & 15);
        rp_b[jj] = (uint32_t)row * 128 + (lnx ^ (uint32_t)((row & 7) * 16));
    }

    LOAD_STAGE(0);
    LOAD_STAGE(1);

    for (int kt = 0; kt < NKITER; kt++) {
        const int s = kt % 3;
        CP_WAIT1();
        __syncthreads();
        if (kt + 2 < NKITER) LOAD_STAGE((kt + 2) % 3);

        const uint32_t abase = sb + (uint32_t)s * STAGE_B;
        const uint32_t bbase = abase + A_STG;
        #pragma unroll
        for (int ks = 0; ks < 4; ks++) {
            const uint32_t kx = (uint32_t)ks << 5;
            uint32_t a[2][4];
            #pragma unroll
            for (int i = 0; i < 2; i++)
                ldmx4(a[i], abase + (rp_a[i] ^ kx));
            uint32_t b[4][2];
            #pragma unroll
            for (int jj = 0; jj < 2; jj++) {
                uint32_t r[4];
                ldmx4(r, bbase + (rp_b[jj] ^ kx));
                b[2*jj][0]   = r[0]; b[2*jj][1]   = r[2];
                b[2*jj+1][0] = r[1]; b[2*jj+1][1] = r[3];
            }
            #pragma unroll
            for (int i = 0; i < 2; i++)
                #pragma unroll
                for (int j = 0; j < 4; j++)
                    mma16816(acc[i][j], a[i], b[j]);
        }
    }

    // epilogue: bias add, store scores, per-row partial sum of exp
    #pragma unroll
    for (int i = 0; i < 2; i++) {
        const int row = bm + wm * 32 + i * 16 + (lane >> 2);
        float s0 = 0.f, s1 = 0.f;       // rows row, row+8
        #pragma unroll
        for (int j = 0; j < 4; j++) {
            const int col = bn + wn * 32 + j * 8 + (lane & 3) * 2;
            const float b0 = bias[col], b1 = bias[col + 1];
            float v00 = acc[i][j][0] + b0, v01 = acc[i][j][1] + b1;
            float v10 = acc[i][j][2] + b0, v11 = acc[i][j][3] + b1;
            *(float2*)(g_scores + (size_t)row * NV + col)       = make_float2(v00, v01);
            *(float2*)(g_scores + (size_t)(row + 8) * NV + col) = make_float2(v10, v11);
            s0 += ((col == 0) ? 0.f : __expf(v00)) + __expf(v01);
            s1 += ((col == 0) ? 0.f : __expf(v10)) + __expf(v11);
        }
        s0 += __shfl_xor_sync(0xffffffff, s0, 1);
        s0 += __shfl_xor_sync(0xffffffff, s0, 2);
        s1 += __shfl_xor_sync(0xffffffff, s1, 1);
        s1 += __shfl_xor_sync(0xffffffff, s1, 2);
        if ((lane & 3) == 0) {
            atomicAdd(&g_sumexp[row],     s0);
            atomicAdd(&g_sumexp[row + 8], s1);
        }
    }
}

// ---------------------------------------------------------------------------
// Finalize: 2 blocks per row (vocab halves); copy regions on half 1.
// Argmax via packed u64 atomicMax: (prob_bits<<32) | (~idx) — positive
// floats are bit-monotonic; ties resolve to lowest index.
// ---------------------------------------------------------------------------
__global__ __launch_bounds__(256)
void finalize_kernel(const float* __restrict__ satt,
                     const float* __restrict__ tatt,
                     float* __restrict__ out) {
    const int row  = blockIdx.y;
    const int half = blockIdx.x;
    const int b    = row / NT;
    const int tid  = threadIdx.x;

    __shared__ float red[256];
    __shared__ int   redi[256];
    __shared__ float src_acc[NSDV];
    __shared__ float tgt_acc[NTDV];

    const float pg    = g_p[row*3+2];
    const float scale = pg / g_sumexp[row];

    float* orow = out + (size_t)row * NOUT;
    float  bmax = -1.f;
    int    bidx = 0;

    if (half == 1) {
        // copy regions (scatter + write + local argmax)
        const float pcs = g_p[row*3+0];
        const float pct = g_p[row*3+1];
        for (int i = tid; i < NSDV; i += 256) src_acc[i] = 0.f;
        for (int i = tid; i < NTDV; i += 256) tgt_acc[i] = 0.f;
        __syncthreads();
        for (int s = tid; s < NS; s += 256)
            atomicAdd(&src_acc[g_src_idx[b*NS + s]], satt[(size_t)row*NS + s]);
        for (int n = tid; n < NT; n += 256)
            atomicAdd(&tgt_acc[g_tgt_idx[b*NT + n]], tatt[(size_t)row*NTDV + n]);
        __syncthreads();
        for (int v = tid; v < NSDV; v += 256) {
            float pv = pcs * src_acc[v];
            orow[NV + v] = pv;
            int gi = NV + v;
            if (pv > bmax || (pv == bmax && gi < bidx)) { bmax = pv; bidx = gi; }
        }
        for (int v = tid; v < NTDV; v += 256) {
            float pv = pct * tgt_acc[v];
            orow[NV + NSDV + v] = pv;
            int gi = NV + NSDV + v;
            if (pv > bmax || (pv == bmax && gi < bidx)) { bmax = pv; bidx = gi; }
        }
    }

    // vocab half: [half*4000, half*4000+4000) float4s
    const float4* srow4 = (const float4*)(g_scores + (size_t)row * NV);
    float4* orow4 = (float4*)orow;
    const int i0 = half * (NV/8);        // in float4 units
    for (int i = i0 + tid; i < i0 + NV/8; i += 256) {
        float4 v = srow4[i];
        float4 p;
        p.x = __expf(v.x) * scale;
        p.y = __expf(v.y) * scale;
        p.z = __expf(v.z) * scale;
        p.w = __expf(v.w) * scale;
        if (i == 0) p.x = 0.f;
        orow4[i] = p;
        int base = i * 4;
        if (p.x > bmax) { bmax = p.x; bidx = base;   }
        if (p.y > bmax) { bmax = p.y; bidx = base+1; }
        if (p.z > bmax) { bmax = p.z; bidx = base+2; }
        if (p.w > bmax) { bmax = p.w; bidx = base+3; }
    }

    red[tid]  = bmax;
    redi[tid] = bidx;
    __syncthreads();
    for (int o = 128; o > 0; o >>= 1) {
        if (tid < o) {
            float v2 = red[tid + o]; int i2 = redi[tid + o];
            if (v2 > red[tid] || (v2 == red[tid] && i2 < redi[tid])) {
                red[tid] = v2; redi[tid] = i2;
            }
        }
        __syncthreads();
    }
    if (tid == 0) {
        unsigned long long pk =
            ((unsigned long long)__float_as_uint(red[0]) << 32)
            | (unsigned long long)(0xFFFFFFFFu - (uint32_t)redi[0]);
        atomicMax(&g_amax[row], pk);
    }
}

// ---------------------------------------------------------------------------
__global__ void pred_kernel(float* __restrict__ out) {
    int row = blockIdx.x * blockDim.x + threadIdx.x;
    if (row >= MM) return;
    out[(size_t)MM * NOUT + row] =
        (float)(0xFFFFFFFFu - (uint32_t)g_amax[row]);
}

// ---------------------------------------------------------------------------
extern "C" void kernel_launch(void* const* d_in, const int* in_sizes, int n_in,
                              void* d_out, int out_size) {
    const float* hiddens = (const float*)d_in[0];
    const float* Wp      = (const float*)d_in[1];
    const float* bp      = (const float*)d_in[2];
    const float* Wv      = (const float*)d_in[3];
    const float* bv      = (const float*)d_in[4];
    const float* satt    = (const float*)d_in[5];
    const float* smap    = (const float*)d_in[6];
    const float* tatt    = (const float*)d_in[7];
    const float* tmap    = (const float*)d_in[8];
    float* out = (float*)d_out;

    cudaFuncSetAttribute(gemm_mma_kernel,
                         cudaFuncAttributeMaxDynamicSharedMemorySize, SMEM_GEMM);

    // gemm in launch slot 4 -> gets ncu-captured
    convB_kernel<<<dim3(NV/32, NH/32), dim3(32, 8)>>>(Wv);     // 1
    p_conv_kernel<<<MM/4, 128>>>(hiddens, Wp, bp);             // 2
    prep_idx_kernel<<<8, 256>>>(smap, tmap);                   // 3
    gemm_mma_kernel<<<dim3(NV/BN, MM/BM), 256, SMEM_GEMM>>>(bv); // 4
    finalize_kernel<<<dim3(2, MM), 256>>>(satt, tatt, out);    // 5
    pred_kernel<<<8, 256>>>(out);                              // 6
}